// round 4
// baseline (speedup 1.0000x reference)
#include <cuda_runtime.h>
#include <math.h>

// ============================================================================
// PCLinear: Polar-Express preconditioned linear layer.
//   gram = W W^T ; w_norm = ||gram^2||_F^0.25 + 1e-8 ; Wn = W / w_norm
//   8x: T = b*(Wn^T Wn) + c*(Wn^T Wn)^2 ; Wn = a*Wn + Wn T
//   out = (w_norm * gamma) * X @ Wn^T
// All fp32. Scratch lives in __device__ globals (no allocations).
// SGEMM: 128x128x8 tiles, 256 thr, 8x8/thread, double-buffered smem.
//
// R3 fix: B-operand tile loads use the OPPOSITE transpose convention from A
// (ld_tile<!TB>), since opB(k,n) contiguity is inverted vs opA(m,k).
// ============================================================================

#define NDIM 2048
#define MAT  (NDIM * NDIM)

__device__ float g_buf0[MAT];   // gram / wtw
__device__ float g_buf1[MAT];   // gram^2 / T
__device__ float g_buf2[MAT];   // W (ping)
__device__ float g_buf3[MAT];   // W (pong)
__device__ double g_accum;
__device__ float  g_scalars[3]; // [0]=w_norm [1]=1/w_norm [2]=w_norm*gamma

// ----------------------------------------------------------------------------
// Tile-load helpers.
// KK_SLOW=true : tile dim 'rc' is contiguous in memory at fixed k.
//                load P[(k0+kk)*ld + rc0+rv], float4 over rc.   (8 kk x 32 thr)
// KK_SLOW=false: k is contiguous in memory at fixed rc.
//                load P[(rc0+r)*ld + k0+kv], float4 over k, scatter. (128 r x 2)
// Target smem layout is always S[kk][rc].
// For A (opA(m,k)):  TA=true -> m contiguous -> KK_SLOW=true.   Use <TA>.
// For B (opB(k,n)):  TB=false -> n contiguous -> KK_SLOW=true.  Use <!TB>.
// ----------------------------------------------------------------------------
template<bool KK_SLOW>
__device__ __forceinline__ float4 ld_tile(const float* __restrict__ P, int ld,
                                          int rc0, int k0, int tid)
{
    if (KK_SLOW) {
        int kk = tid >> 5;                 // 0..7
        int rv = (tid & 31) << 2;          // 0..124
        return *reinterpret_cast<const float4*>(P + (size_t)(k0 + kk) * ld + rc0 + rv);
    } else {
        int r  = tid >> 1;                 // 0..127
        int kv = (tid & 1) << 2;           // 0 or 4
        return *reinterpret_cast<const float4*>(P + (size_t)(rc0 + r) * ld + k0 + kv);
    }
}

template<bool KK_SLOW>
__device__ __forceinline__ void st_tile(float (*S)[128], float4 v, int tid)
{
    if (KK_SLOW) {
        int kk = tid >> 5;
        int rv = (tid & 31) << 2;
        *reinterpret_cast<float4*>(&S[kk][rv]) = v;
    } else {
        int r  = tid >> 1;
        int kv = (tid & 1) << 2;
        S[kv + 0][r] = v.x; S[kv + 1][r] = v.y;
        S[kv + 2][r] = v.z; S[kv + 3][r] = v.w;
    }
}

// ----------------------------------------------------------------------------
// Generic SGEMM: C[M,N] = alphaEff * op(A) @ op(B) + beta * D   (D optional)
//   TA=false: opA(m,k)=A[m*lda+k]   TA=true: opA(m,k)=A[k*lda+m]
//   TB=false: opB(k,n)=B[k*ldb+n]   TB=true: opB(k,n)=B[n*ldb+k]
// alphaIdx >= 0 -> alphaEff = alpha * g_scalars[alphaIdx] (runtime scalar).
// ----------------------------------------------------------------------------
template<bool TA, bool TB>
__global__ __launch_bounds__(256, 2)
void sgemm_kernel(const float* __restrict__ A, int lda,
                  const float* __restrict__ B, int ldb,
                  const float* __restrict__ D,
                  float* __restrict__ C, int ldc,
                  int K, float alpha, float beta, int alphaIdx)
{
    __shared__ float As[2][8][128];
    __shared__ float Bs[2][8][128];

    const int tid  = threadIdx.x;
    const int row0 = blockIdx.y * 128;
    const int col0 = blockIdx.x * 128;
    const int tx   = tid & 15;   // 0..15 -> 8 cols each
    const int ty   = tid >> 4;   // 0..15 -> 8 rows each

    float acc[8][8];
    #pragma unroll
    for (int i = 0; i < 8; i++)
        #pragma unroll
        for (int j = 0; j < 8; j++) acc[i][j] = 0.0f;

    // prologue: load first tile into buffer 0
    float4 av = ld_tile<TA>(A, lda, row0, 0, tid);
    float4 bv = ld_tile<!TB>(B, ldb, col0, 0, tid);
    st_tile<TA>(As[0], av, tid);
    st_tile<!TB>(Bs[0], bv, tid);
    __syncthreads();

    int buf = 0;
    for (int k0 = 0; k0 < K; k0 += 8) {
        const bool has_next = (k0 + 8) < K;
        if (has_next) {
            av = ld_tile<TA>(A, lda, row0, k0 + 8, tid);
            bv = ld_tile<!TB>(B, ldb, col0, k0 + 8, tid);
        }

        #pragma unroll
        for (int kk = 0; kk < 8; kk++) {
            float a[8], b[8];
            *reinterpret_cast<float4*>(&a[0]) =
                *reinterpret_cast<const float4*>(&As[buf][kk][ty * 8 + 0]);
            *reinterpret_cast<float4*>(&a[4]) =
                *reinterpret_cast<const float4*>(&As[buf][kk][ty * 8 + 4]);
            *reinterpret_cast<float4*>(&b[0]) =
                *reinterpret_cast<const float4*>(&Bs[buf][kk][tx * 8 + 0]);
            *reinterpret_cast<float4*>(&b[4]) =
                *reinterpret_cast<const float4*>(&Bs[buf][kk][tx * 8 + 4]);
            #pragma unroll
            for (int i = 0; i < 8; i++)
                #pragma unroll
                for (int j = 0; j < 8; j++)
                    acc[i][j] = fmaf(a[i], b[j], acc[i][j]);
        }

        if (has_next) {
            st_tile<TA>(As[buf ^ 1], av, tid);
            st_tile<!TB>(Bs[buf ^ 1], bv, tid);
            __syncthreads();
            buf ^= 1;
        }
    }

    float aEff = alpha;
    if (alphaIdx >= 0) aEff *= g_scalars[alphaIdx];

    #pragma unroll
    for (int i = 0; i < 8; i++) {
        int m = row0 + ty * 8 + i;
        #pragma unroll
        for (int j = 0; j < 8; j += 4) {
            int n = col0 + tx * 8 + j;
            float4 v;
            v.x = aEff * acc[i][j + 0];
            v.y = aEff * acc[i][j + 1];
            v.z = aEff * acc[i][j + 2];
            v.w = aEff * acc[i][j + 3];
            if (D) {
                float4 d = *reinterpret_cast<const float4*>(D + (size_t)m * ldc + n);
                v.x += beta * d.x; v.y += beta * d.y;
                v.z += beta * d.z; v.w += beta * d.w;
            }
            *reinterpret_cast<float4*>(C + (size_t)m * ldc + n) = v;
        }
    }
}

// ----------------------------------------------------------------------------
// Reduction + scalar kernels
// ----------------------------------------------------------------------------
__global__ void zero_accum_kernel() { g_accum = 0.0; }

__global__ void sumsq_kernel(const float* __restrict__ A, int n)
{
    double s = 0.0;
    for (int i = blockIdx.x * blockDim.x + threadIdx.x; i < n;
         i += gridDim.x * blockDim.x) {
        float v = A[i];
        s += (double)v * (double)v;
    }
    #pragma unroll
    for (int o = 16; o > 0; o >>= 1) s += __shfl_down_sync(0xffffffffu, s, o);
    __shared__ double ws[8];
    int lane = threadIdx.x & 31, w = threadIdx.x >> 5;
    if (lane == 0) ws[w] = s;
    __syncthreads();
    if (w == 0) {
        s = (lane < 8) ? ws[lane] : 0.0;
        #pragma unroll
        for (int o = 4; o > 0; o >>= 1) s += __shfl_down_sync(0xffffffffu, s, o);
        if (lane == 0) atomicAdd(&g_accum, s);
    }
}

__global__ void finalize_kernel(const float* __restrict__ gamma)
{
    double fro2   = g_accum;                 // ||gram^2||_F^2
    double w_norm = pow(fro2, 0.125) + 1e-8; // (fro2^0.5)^0.25 + eps
    g_scalars[0] = (float)w_norm;
    g_scalars[1] = (float)(1.0 / w_norm);
    g_scalars[2] = (float)w_norm * gamma[0];
}

__global__ void scale_kernel(float* __restrict__ W, const float* __restrict__ src)
{
    float s = g_scalars[1];
    int i = (blockIdx.x * blockDim.x + threadIdx.x) * 4;
    float4 v = *reinterpret_cast<const float4*>(src + i);
    v.x *= s; v.y *= s; v.z *= s; v.w *= s;
    *reinterpret_cast<float4*>(W + i) = v;
}

// ----------------------------------------------------------------------------
// Host orchestration (graph-capturable: kernel launches only)
// ----------------------------------------------------------------------------
static inline void run_gemm(bool ta, bool tb,
                            const float* A, int lda, const float* B, int ldb,
                            const float* D, float* C, int ldc,
                            int M, int N, int K,
                            float alpha, float beta, int alphaIdx)
{
    dim3 grid(N / 128, M / 128), block(256);
    if (!ta && !tb)
        sgemm_kernel<false, false><<<grid, block>>>(A, lda, B, ldb, D, C, ldc, K, alpha, beta, alphaIdx);
    else if (!ta && tb)
        sgemm_kernel<false, true ><<<grid, block>>>(A, lda, B, ldb, D, C, ldc, K, alpha, beta, alphaIdx);
    else if (ta && !tb)
        sgemm_kernel<true,  false><<<grid, block>>>(A, lda, B, ldb, D, C, ldc, K, alpha, beta, alphaIdx);
    else
        sgemm_kernel<true,  true ><<<grid, block>>>(A, lda, B, ldb, D, C, ldc, K, alpha, beta, alphaIdx);
}

static const float PE_COEF[8][3] = {
    {7.2086f, -15.5131f, 9.0178f}, {3.9623f, -2.5813f, 0.4542f},
    {3.9466f, -2.5765f, 0.4544f}, {3.8991f, -2.5671f, 0.4566f},
    {3.7186f, -2.5308f, 0.4653f}, {3.1390f, -2.3073f, 0.4733f},
    {2.1715f, -1.5246f, 0.3885f}, {1.8648f, -1.2224f, 0.3577f},
};

extern "C" void kernel_launch(void* const* d_in, const int* in_sizes, int n_in,
                              void* d_out, int out_size)
{
    const float* x      = (const float*)d_in[0];
    const float* weight = (const float*)d_in[1];
    const float* gamma  = (const float*)d_in[2];
    float*       out    = (float*)d_out;

    float *b0, *b1, *b2, *b3;
    cudaGetSymbolAddress((void**)&b0, g_buf0);
    cudaGetSymbolAddress((void**)&b1, g_buf1);
    cudaGetSymbolAddress((void**)&b2, g_buf2);
    cudaGetSymbolAddress((void**)&b3, g_buf3);

    const int N = NDIM;
    const int M_out = in_sizes[0] / N;   // 4*2048 = 8192 rows of X

    // ---- w_norm = ||(W W^T)^2||_F^0.25 + eps ----
    zero_accum_kernel<<<1, 1>>>();
    run_gemm(false, true,  weight, N, weight, N, nullptr, b0, N, N, N, N, 1.0f, 0.0f, -1); // gram = W W^T
    run_gemm(false, false, b0,     N, b0,     N, nullptr, b1, N, N, N, N, 1.0f, 0.0f, -1); // gram^2
    sumsq_kernel<<<1024, 256>>>(b1, MAT);
    finalize_kernel<<<1, 1>>>(gamma);

    // ---- W = weight / w_norm ----
    scale_kernel<<<MAT / 4 / 256, 256>>>(b2, weight);

    // ---- 8 Polar Express iterations ----
    float* W  = b2;
    float* Wn = b3;
    for (int it = 0; it < 8; it++) {
        float a = PE_COEF[it][0], bb = PE_COEF[it][1], c = PE_COEF[it][2];
        // wtw = W^T W
        run_gemm(true,  false, W,  N, W,  N, nullptr, b0, N, N, N, N, 1.0f, 0.0f, -1);
        // T = c * wtw@wtw + b * wtw
        run_gemm(false, false, b0, N, b0, N, b0,      b1, N, N, N, N, c,    bb,   -1);
        // Wn = W @ T + a * W
        run_gemm(false, false, W,  N, b1, N, W,       Wn, N, N, N, N, 1.0f, a,    -1);
        float* t = W; W = Wn; Wn = t;
    }

    // ---- out = (w_norm * gamma) * X @ W^T ----
    run_gemm(false, true, x, N, W, N, nullptr, out, N, M_out, N, N, 1.0f, 0.0f, 2);
}

// round 5
// speedup vs baseline: 1.0008x; 1.0008x over previous
#include <cuda_runtime.h>
#include <math.h>

// ============================================================================
// PCLinear: Polar-Express preconditioned linear layer.
//   gram = W W^T ; w_norm = ||gram^2||_F^0.25 + 1e-8 ; Wn = W / w_norm
//   8x: T = b*(Wn^T Wn) + c*(Wn^T Wn)^2 ; Wn = a*Wn + Wn T
//   out = (w_norm * gamma) * X @ Wn^T
// All fp32. Scratch lives in __device__ globals (no allocations).
// SGEMM: 128x128x8 tiles, 256 thr, 8x8/thread, double-buffered smem.
//
// R3 fix: B-operand tile loads use the OPPOSITE transpose convention from A
// (ld_tile<!TB>), since opB(k,n) contiguity is inverted vs opA(m,k).
// ============================================================================

#define NDIM 2048
#define MAT  (NDIM * NDIM)

__device__ float g_buf0[MAT];   // gram / wtw
__device__ float g_buf1[MAT];   // gram^2 / T
__device__ float g_buf2[MAT];   // W (ping)
__device__ float g_buf3[MAT];   // W (pong)
__device__ double g_accum;
__device__ float  g_scalars[3]; // [0]=w_norm [1]=1/w_norm [2]=w_norm*gamma

// ----------------------------------------------------------------------------
// Tile-load helpers.
// KK_SLOW=true : tile dim 'rc' is contiguous in memory at fixed k.
//                load P[(k0+kk)*ld + rc0+rv], float4 over rc.   (8 kk x 32 thr)
// KK_SLOW=false: k is contiguous in memory at fixed rc.
//                load P[(rc0+r)*ld + k0+kv], float4 over k, scatter. (128 r x 2)
// Target smem layout is always S[kk][rc].
// For A (opA(m,k)):  TA=true -> m contiguous -> KK_SLOW=true.   Use <TA>.
// For B (opB(k,n)):  TB=false -> n contiguous -> KK_SLOW=true.  Use <!TB>.
// ----------------------------------------------------------------------------
template<bool KK_SLOW>
__device__ __forceinline__ float4 ld_tile(const float* __restrict__ P, int ld,
                                          int rc0, int k0, int tid)
{
    if (KK_SLOW) {
        int kk = tid >> 5;                 // 0..7
        int rv = (tid & 31) << 2;          // 0..124
        return *reinterpret_cast<const float4*>(P + (size_t)(k0 + kk) * ld + rc0 + rv);
    } else {
        int r  = tid >> 1;                 // 0..127
        int kv = (tid & 1) << 2;           // 0 or 4
        return *reinterpret_cast<const float4*>(P + (size_t)(rc0 + r) * ld + k0 + kv);
    }
}

template<bool KK_SLOW>
__device__ __forceinline__ void st_tile(float (*S)[128], float4 v, int tid)
{
    if (KK_SLOW) {
        int kk = tid >> 5;
        int rv = (tid & 31) << 2;
        *reinterpret_cast<float4*>(&S[kk][rv]) = v;
    } else {
        int r  = tid >> 1;
        int kv = (tid & 1) << 2;
        S[kv + 0][r] = v.x; S[kv + 1][r] = v.y;
        S[kv + 2][r] = v.z; S[kv + 3][r] = v.w;
    }
}

// ----------------------------------------------------------------------------
// Generic SGEMM: C[M,N] = alphaEff * op(A) @ op(B) + beta * D   (D optional)
//   TA=false: opA(m,k)=A[m*lda+k]   TA=true: opA(m,k)=A[k*lda+m]
//   TB=false: opB(k,n)=B[k*ldb+n]   TB=true: opB(k,n)=B[n*ldb+k]
// alphaIdx >= 0 -> alphaEff = alpha * g_scalars[alphaIdx] (runtime scalar).
// ----------------------------------------------------------------------------
template<bool TA, bool TB>
__global__ __launch_bounds__(256, 2)
void sgemm_kernel(const float* __restrict__ A, int lda,
                  const float* __restrict__ B, int ldb,
                  const float* __restrict__ D,
                  float* __restrict__ C, int ldc,
                  int K, float alpha, float beta, int alphaIdx)
{
    __shared__ float As[2][8][128];
    __shared__ float Bs[2][8][128];

    const int tid  = threadIdx.x;
    const int row0 = blockIdx.y * 128;
    const int col0 = blockIdx.x * 128;
    const int tx   = tid & 15;   // 0..15 -> 8 cols each
    const int ty   = tid >> 4;   // 0..15 -> 8 rows each

    float acc[8][8];
    #pragma unroll
    for (int i = 0; i < 8; i++)
        #pragma unroll
        for (int j = 0; j < 8; j++) acc[i][j] = 0.0f;

    // prologue: load first tile into buffer 0
    float4 av = ld_tile<TA>(A, lda, row0, 0, tid);
    float4 bv = ld_tile<!TB>(B, ldb, col0, 0, tid);
    st_tile<TA>(As[0], av, tid);
    st_tile<!TB>(Bs[0], bv, tid);
    __syncthreads();

    int buf = 0;
    for (int k0 = 0; k0 < K; k0 += 8) {
        const bool has_next = (k0 + 8) < K;
        if (has_next) {
            av = ld_tile<TA>(A, lda, row0, k0 + 8, tid);
            bv = ld_tile<!TB>(B, ldb, col0, k0 + 8, tid);
        }

        #pragma unroll
        for (int kk = 0; kk < 8; kk++) {
            float a[8], b[8];
            *reinterpret_cast<float4*>(&a[0]) =
                *reinterpret_cast<const float4*>(&As[buf][kk][ty * 8 + 0]);
            *reinterpret_cast<float4*>(&a[4]) =
                *reinterpret_cast<const float4*>(&As[buf][kk][ty * 8 + 4]);
            *reinterpret_cast<float4*>(&b[0]) =
                *reinterpret_cast<const float4*>(&Bs[buf][kk][tx * 8 + 0]);
            *reinterpret_cast<float4*>(&b[4]) =
                *reinterpret_cast<const float4*>(&Bs[buf][kk][tx * 8 + 4]);
            #pragma unroll
            for (int i = 0; i < 8; i++)
                #pragma unroll
                for (int j = 0; j < 8; j++)
                    acc[i][j] = fmaf(a[i], b[j], acc[i][j]);
        }

        if (has_next) {
            st_tile<TA>(As[buf ^ 1], av, tid);
            st_tile<!TB>(Bs[buf ^ 1], bv, tid);
            __syncthreads();
            buf ^= 1;
        }
    }

    float aEff = alpha;
    if (alphaIdx >= 0) aEff *= g_scalars[alphaIdx];

    #pragma unroll
    for (int i = 0; i < 8; i++) {
        int m = row0 + ty * 8 + i;
        #pragma unroll
        for (int j = 0; j < 8; j += 4) {
            int n = col0 + tx * 8 + j;
            float4 v;
            v.x = aEff * acc[i][j + 0];
            v.y = aEff * acc[i][j + 1];
            v.z = aEff * acc[i][j + 2];
            v.w = aEff * acc[i][j + 3];
            if (D) {
                float4 d = *reinterpret_cast<const float4*>(D + (size_t)m * ldc + n);
                v.x += beta * d.x; v.y += beta * d.y;
                v.z += beta * d.z; v.w += beta * d.w;
            }
            *reinterpret_cast<float4*>(C + (size_t)m * ldc + n) = v;
        }
    }
}

// ----------------------------------------------------------------------------
// Reduction + scalar kernels
// ----------------------------------------------------------------------------
__global__ void zero_accum_kernel() { g_accum = 0.0; }

__global__ void sumsq_kernel(const float* __restrict__ A, int n)
{
    double s = 0.0;
    for (int i = blockIdx.x * blockDim.x + threadIdx.x; i < n;
         i += gridDim.x * blockDim.x) {
        float v = A[i];
        s += (double)v * (double)v;
    }
    #pragma unroll
    for (int o = 16; o > 0; o >>= 1) s += __shfl_down_sync(0xffffffffu, s, o);
    __shared__ double ws[8];
    int lane = threadIdx.x & 31, w = threadIdx.x >> 5;
    if (lane == 0) ws[w] = s;
    __syncthreads();
    if (w == 0) {
        s = (lane < 8) ? ws[lane] : 0.0;
        #pragma unroll
        for (int o = 4; o > 0; o >>= 1) s += __shfl_down_sync(0xffffffffu, s, o);
        if (lane == 0) atomicAdd(&g_accum, s);
    }
}

__global__ void finalize_kernel(const float* __restrict__ gamma)
{
    double fro2   = g_accum;                 // ||gram^2||_F^2
    double w_norm = pow(fro2, 0.125) + 1e-8; // (fro2^0.5)^0.25 + eps
    g_scalars[0] = (float)w_norm;
    g_scalars[1] = (float)(1.0 / w_norm);
    g_scalars[2] = (float)w_norm * gamma[0];
}

__global__ void scale_kernel(float* __restrict__ W, const float* __restrict__ src)
{
    float s = g_scalars[1];
    int i = (blockIdx.x * blockDim.x + threadIdx.x) * 4;
    float4 v = *reinterpret_cast<const float4*>(src + i);
    v.x *= s; v.y *= s; v.z *= s; v.w *= s;
    *reinterpret_cast<float4*>(W + i) = v;
}

// ----------------------------------------------------------------------------
// Host orchestration (graph-capturable: kernel launches only)
// ----------------------------------------------------------------------------
static inline void run_gemm(bool ta, bool tb,
                            const float* A, int lda, const float* B, int ldb,
                            const float* D, float* C, int ldc,
                            int M, int N, int K,
                            float alpha, float beta, int alphaIdx)
{
    dim3 grid(N / 128, M / 128), block(256);
    if (!ta && !tb)
        sgemm_kernel<false, false><<<grid, block>>>(A, lda, B, ldb, D, C, ldc, K, alpha, beta, alphaIdx);
    else if (!ta && tb)
        sgemm_kernel<false, true ><<<grid, block>>>(A, lda, B, ldb, D, C, ldc, K, alpha, beta, alphaIdx);
    else if (ta && !tb)
        sgemm_kernel<true,  false><<<grid, block>>>(A, lda, B, ldb, D, C, ldc, K, alpha, beta, alphaIdx);
    else
        sgemm_kernel<true,  true ><<<grid, block>>>(A, lda, B, ldb, D, C, ldc, K, alpha, beta, alphaIdx);
}

static const float PE_COEF[8][3] = {
    {7.2086f, -15.5131f, 9.0178f}, {3.9623f, -2.5813f, 0.4542f},
    {3.9466f, -2.5765f, 0.4544f}, {3.8991f, -2.5671f, 0.4566f},
    {3.7186f, -2.5308f, 0.4653f}, {3.1390f, -2.3073f, 0.4733f},
    {2.1715f, -1.5246f, 0.3885f}, {1.8648f, -1.2224f, 0.3577f},
};

extern "C" void kernel_launch(void* const* d_in, const int* in_sizes, int n_in,
                              void* d_out, int out_size)
{
    const float* x      = (const float*)d_in[0];
    const float* weight = (const float*)d_in[1];
    const float* gamma  = (const float*)d_in[2];
    float*       out    = (float*)d_out;

    float *b0, *b1, *b2, *b3;
    cudaGetSymbolAddress((void**)&b0, g_buf0);
    cudaGetSymbolAddress((void**)&b1, g_buf1);
    cudaGetSymbolAddress((void**)&b2, g_buf2);
    cudaGetSymbolAddress((void**)&b3, g_buf3);

    const int N = NDIM;
    const int M_out = in_sizes[0] / N;   // 4*2048 = 8192 rows of X

    // ---- w_norm = ||(W W^T)^2||_F^0.25 + eps ----
    zero_accum_kernel<<<1, 1>>>();
    run_gemm(false, true,  weight, N, weight, N, nullptr, b0, N, N, N, N, 1.0f, 0.0f, -1); // gram = W W^T
    run_gemm(false, false, b0,     N, b0,     N, nullptr, b1, N, N, N, N, 1.0f, 0.0f, -1); // gram^2
    sumsq_kernel<<<1024, 256>>>(b1, MAT);
    finalize_kernel<<<1, 1>>>(gamma);

    // ---- W = weight / w_norm ----
    scale_kernel<<<MAT / 4 / 256, 256>>>(b2, weight);

    // ---- 8 Polar Express iterations ----
    float* W  = b2;
    float* Wn = b3;
    for (int it = 0; it < 8; it++) {
        float a = PE_COEF[it][0], bb = PE_COEF[it][1], c = PE_COEF[it][2];
        // wtw = W^T W
        run_gemm(true,  false, W,  N, W,  N, nullptr, b0, N, N, N, N, 1.0f, 0.0f, -1);
        // T = c * wtw@wtw + b * wtw
        run_gemm(false, false, b0, N, b0, N, b0,      b1, N, N, N, N, c,    bb,   -1);
        // Wn = W @ T + a * W
        run_gemm(false, false, W,  N, b1, N, W,       Wn, N, N, N, N, 1.0f, a,    -1);
        float* t = W; W = Wn; Wn = t;
    }

    // ---- out = (w_norm * gamma) * X @ W^T ----
    run_gemm(false, true, x, N, W, N, nullptr, out, N, M_out, N, N, 1.0f, 0.0f, 2);
}

// round 8
// speedup vs baseline: 2.4219x; 2.4200x over previous
#include <cuda_runtime.h>
#include <cuda_bf16.h>
#include <math.h>
#include <stdint.h>

// ============================================================================
// PCLinear via mma.sync (sm_80-style HMMA, works on base sm_100) with bf16x3
// error-compensated split GEMMs.
//   gram = W W^T ; w_norm = ||gram^2||_F^0.25 + 1e-8 ; U = W / w_norm
//   8x: g = U^T U ; T = b*g + c*g^2 ; U = a*U + U T
//   out = (w_norm * gamma) * X @ U^T
// Every GEMM is C[m,n] = sum_k P[m,k] Q[n,k], P,Q row-major (g/T symmetric;
// U^T kept fresh by a transpose kernel). fp32 value x = hi + lo (bf16 each);
// product via 3 MMAs: hi*hi + hi*lo + lo*hi (error ~2^-18).
// ============================================================================

#define GK     2048
#define MAT    (GK * GK)
#define XROWS  8192
#define XMAT   (XROWS * GK)

#define CHUNK    32
#define NCH      (GK / CHUNK)       // 64
#define LDS_B    80                 // smem row stride bytes (40 bf16) -> conflict-free ldmatrix
#define TILE_B   (128 * LDS_B)      // 10240
#define STAGE_B  (4 * TILE_B)       // Ah, Al, Bh, Bl
#define SMEM_NEED (1024 + 2 * STAGE_B)

// -------------------- device scratch (static, no allocs) --------------------
__device__ __nv_bfloat16 g_wh[MAT],  g_wl[MAT];    // weight split (for gram)
__device__ __nv_bfloat16 g_u0h[MAT], g_u0l[MAT];   // U ping
__device__ __nv_bfloat16 g_u1h[MAT], g_u1l[MAT];   // U pong
__device__ __nv_bfloat16 g_t0h[MAT], g_t0l[MAT];   // U^T ping
__device__ __nv_bfloat16 g_t1h[MAT], g_t1l[MAT];   // U^T pong
__device__ __nv_bfloat16 g_gh[MAT],  g_gl[MAT];    // gram / wtw
__device__ __nv_bfloat16 g_eh[MAT],  g_el[MAT];    // T polynomial
__device__ __nv_bfloat16 g_xh[XMAT], g_xl[XMAT];   // X split
__device__ double g_accum;
__device__ float  g_scalars[3];  // [0]=w_norm [1]=1/w_norm [2]=w_norm*gamma

// -------------------- low-level helpers --------------------
__device__ __forceinline__ uint32_t smem_to_u32(const void* p) {
    uint32_t a;
    asm("{ .reg .u64 t; cvta.to.shared.u64 t, %1; cvt.u32.u64 %0, t; }"
        : "=r"(a) : "l"(p));
    return a;
}
__device__ __forceinline__ void ldsm_x4(uint32_t* r, uint32_t addr) {
    asm volatile("ldmatrix.sync.aligned.m8n8.x4.shared.b16 {%0,%1,%2,%3}, [%4];"
                 : "=r"(r[0]), "=r"(r[1]), "=r"(r[2]), "=r"(r[3]) : "r"(addr));
}
__device__ __forceinline__ void ldsm_x2(uint32_t* r, uint32_t addr) {
    asm volatile("ldmatrix.sync.aligned.m8n8.x2.shared.b16 {%0,%1}, [%2];"
                 : "=r"(r[0]), "=r"(r[1]) : "r"(addr));
}
__device__ __forceinline__ void mma_bf16(float* c, const uint32_t* a, const uint32_t* b) {
    asm volatile("mma.sync.aligned.m16n8k16.row.col.f32.bf16.bf16.f32 "
                 "{%0,%1,%2,%3}, {%4,%5,%6,%7}, {%8,%9}, {%0,%1,%2,%3};"
                 : "+f"(c[0]), "+f"(c[1]), "+f"(c[2]), "+f"(c[3])
                 : "r"(a[0]), "r"(a[1]), "r"(a[2]), "r"(a[3]),
                   "r"(b[0]), "r"(b[1]));
}
__device__ __forceinline__ void cp16(uint32_t dst, const void* src) {
    asm volatile("cp.async.cg.shared.global [%0], [%1], 16;" :: "r"(dst), "l"(src));
}
#define CP_COMMIT() asm volatile("cp.async.commit_group;" ::: "memory")
#define CP_WAIT1()  asm volatile("cp.async.wait_group 1;" ::: "memory")
#define CP_WAIT0()  asm volatile("cp.async.wait_group 0;" ::: "memory")

// ============================================================================
// bf16x3 GEMM: C[m,n] = alphaEff * sum_k (Ah+Al)[m,k]*(Bh+Bl)[n,k]
//              (+ beta*(Dh+Dl)[m,n]); outputs bf16 hi/lo and/or fp32;
//              sumsq mode accumulates ||C||_F^2 into g_accum instead.
// CTA tile 128x128, warp grid 2x4 (warp tile 64x32), K-chunk 32,
// cp.async double-buffered smem, 256 threads.
// ============================================================================
__global__ __launch_bounds__(256, 2)
void gemm_bf16x3_kernel(const __nv_bfloat16* __restrict__ gAh,
                        const __nv_bfloat16* __restrict__ gAl,
                        const __nv_bfloat16* __restrict__ gBh,
                        const __nv_bfloat16* __restrict__ gBl,
                        __nv_bfloat16* __restrict__ oH,
                        __nv_bfloat16* __restrict__ oL,
                        float* __restrict__ oF,
                        const __nv_bfloat16* __restrict__ dH,
                        const __nv_bfloat16* __restrict__ dL,
                        float alpha, float beta, int alphaIdx, int sumsq)
{
    extern __shared__ char smem_raw[];
    const uint32_t smem_u = (smem_to_u32(smem_raw) + 1023u) & ~1023u;

    const int tid  = threadIdx.x;
    const int wid  = tid >> 5;
    const int lane = tid & 31;
    const int wm   = wid >> 2;        // 0..1
    const int wn   = wid & 3;         // 0..3
    const int row0 = blockIdx.y * 128;
    const int col0 = blockIdx.x * 128;

    const __nv_bfloat16* srcs[4] = {gAh, gAl, gBh, gBl};
    const int            rb[4]   = {row0, row0, col0, col0};

    // ldmatrix address cores (byte offsets into a stage)
    const uint32_t aCore = (uint32_t)((lane & 15) * LDS_B + (lane >> 4) * 16
                                      + wm * 64 * LDS_B);
    const uint32_t bCore = (uint32_t)((lane & 7) * LDS_B + ((lane >> 3) & 1) * 16
                                      + wn * 32 * LDS_B) + 2 * TILE_B;

    float acc[4][4][4];
    #pragma unroll
    for (int mt = 0; mt < 4; mt++)
        #pragma unroll
        for (int nt = 0; nt < 4; nt++)
            #pragma unroll
            for (int i = 0; i < 4; i++) acc[mt][nt][i] = 0.0f;

    auto issue_chunk = [&](int ch, int buf) {
        const int k0 = ch * CHUNK;
        const uint32_t sbase = smem_u + buf * STAGE_B;
        #pragma unroll
        for (int t = 0; t < 4; t++) {
            #pragma unroll
            for (int i = 0; i < 2; i++) {
                int id  = tid + i * 256;          // 0..511
                int r   = id >> 2;                // 0..127
                int c16 = id & 3;                 // 0..3 (16B units)
                const void* src = srcs[t] + (size_t)(rb[t] + r) * GK + k0 + c16 * 8;
                uint32_t dst = sbase + t * TILE_B + (uint32_t)(r * LDS_B + c16 * 16);
                cp16(dst, src);
            }
        }
        CP_COMMIT();
    };

    issue_chunk(0, 0);
    for (int ch = 0; ch < NCH; ch++) {
        const int buf = ch & 1;
        if (ch + 1 < NCH) { issue_chunk(ch + 1, buf ^ 1); CP_WAIT1(); }
        else              { CP_WAIT0(); }
        __syncthreads();

        const uint32_t sb = smem_u + buf * STAGE_B;
        #pragma unroll
        for (int ks = 0; ks < 2; ks++) {
            const uint32_t kof = ks * 32;        // 16 bf16 = 32 bytes
            uint32_t bh[4][2], bl[4][2], af[4][4];
            #pragma unroll
            for (int nt = 0; nt < 4; nt++) {
                ldsm_x2(bh[nt], sb + bCore + nt * 8 * LDS_B + kof);
                ldsm_x2(bl[nt], sb + bCore + TILE_B + nt * 8 * LDS_B + kof);
            }
            #pragma unroll
            for (int mt = 0; mt < 4; mt++)
                ldsm_x4(af[mt], sb + aCore + mt * 16 * LDS_B + kof);
            #pragma unroll
            for (int mt = 0; mt < 4; mt++)
                #pragma unroll
                for (int nt = 0; nt < 4; nt++) {
                    mma_bf16(acc[mt][nt], af[mt], bh[nt]);
                    mma_bf16(acc[mt][nt], af[mt], bl[nt]);
                }
            #pragma unroll
            for (int mt = 0; mt < 4; mt++)
                ldsm_x4(af[mt], sb + aCore + TILE_B + mt * 16 * LDS_B + kof);
            #pragma unroll
            for (int mt = 0; mt < 4; mt++)
                #pragma unroll
                for (int nt = 0; nt < 4; nt++)
                    mma_bf16(acc[mt][nt], af[mt], bh[nt]);
        }
        __syncthreads();
    }

    // -------- epilogue --------
    float aEff = alpha;
    if (alphaIdx >= 0) aEff *= g_scalars[alphaIdx];
    const int gid = lane >> 2, tig = lane & 3;
    const int rowBase = row0 + wm * 64;
    const int colBase = col0 + wn * 32;

    if (sumsq) {
        double s = 0.0;
        #pragma unroll
        for (int mt = 0; mt < 4; mt++)
            #pragma unroll
            for (int nt = 0; nt < 4; nt++)
                #pragma unroll
                for (int i = 0; i < 4; i++) {
                    float v = acc[mt][nt][i];
                    s += (double)v * (double)v;
                }
        #pragma unroll
        for (int o = 16; o > 0; o >>= 1) s += __shfl_down_sync(0xffffffffu, s, o);
        double* sred = reinterpret_cast<double*>(smem_raw);
        if (lane == 0) sred[wid] = s;
        __syncthreads();
        if (wid == 0) {
            s = (lane < 8) ? sred[lane] : 0.0;
            #pragma unroll
            for (int o = 4; o > 0; o >>= 1) s += __shfl_down_sync(0xffffffffu, s, o);
            if (lane == 0) atomicAdd(&g_accum, s);
        }
    } else {
        #pragma unroll
        for (int mt = 0; mt < 4; mt++)
            #pragma unroll
            for (int nt = 0; nt < 4; nt++)
                #pragma unroll
                for (int h = 0; h < 2; h++) {
                    const int r  = rowBase + mt * 16 + gid + h * 8;
                    const int cc = colBase + nt * 8 + tig * 2;
                    const size_t ro = (size_t)r * GK + cc;
                    float v0 = aEff * acc[mt][nt][2 * h];
                    float v1 = aEff * acc[mt][nt][2 * h + 1];
                    if (dH) {
                        __nv_bfloat162 h2 = *reinterpret_cast<const __nv_bfloat162*>(dH + ro);
                        __nv_bfloat162 l2 = *reinterpret_cast<const __nv_bfloat162*>(dL + ro);
                        v0 += beta * (__bfloat162float(h2.x) + __bfloat162float(l2.x));
                        v1 += beta * (__bfloat162float(h2.y) + __bfloat162float(l2.y));
                    }
                    if (oF)
                        *reinterpret_cast<float2*>(oF + ro) = make_float2(v0, v1);
                    if (oH) {
                        __nv_bfloat16 h0 = __float2bfloat16(v0);
                        __nv_bfloat16 h1 = __float2bfloat16(v1);
                        __nv_bfloat16 l0 = __float2bfloat16(v0 - __bfloat162float(h0));
                        __nv_bfloat16 l1 = __float2bfloat16(v1 - __bfloat162float(h1));
                        *reinterpret_cast<__nv_bfloat162*>(oH + ro) = __halves2bfloat162(h0, h1);
                        *reinterpret_cast<__nv_bfloat162*>(oL + ro) = __halves2bfloat162(l0, l1);
                    }
                }
    }
}

// ============================================================================
// Elementwise kernels
// ============================================================================
__global__ void zero_accum_kernel() { g_accum = 0.0; }

__global__ void finalize_kernel(const float* __restrict__ gamma)
{
    double fro2   = g_accum;                  // ||gram^2||_F^2
    double w_norm = pow(fro2, 0.125) + 1e-8;  // (fro2^0.5)^0.25 + eps
    g_scalars[0] = (float)w_norm;
    g_scalars[1] = (float)(1.0 / w_norm);
    g_scalars[2] = (float)w_norm * gamma[0];
}

// split fp32 -> (hi, lo) bf16 pair, with optional runtime scale g_scalars[idx]
__global__ void split_kernel(const float* __restrict__ src,
                             __nv_bfloat16* __restrict__ dHo,
                             __nv_bfloat16* __restrict__ dLo, int scaleIdx)
{
    float s = (scaleIdx >= 0) ? g_scalars[scaleIdx] : 1.0f;
    size_t i = ((size_t)blockIdx.x * 256 + threadIdx.x) * 4;
    float4 v = *reinterpret_cast<const float4*>(src + i);
    float f[4] = {v.x * s, v.y * s, v.z * s, v.w * s};
    __nv_bfloat16 h[4], l[4];
    #pragma unroll
    for (int j = 0; j < 4; j++) {
        h[j] = __float2bfloat16(f[j]);
        l[j] = __float2bfloat16(f[j] - __bfloat162float(h[j]));
    }
    *reinterpret_cast<__nv_bfloat162*>(dHo + i)     = __halves2bfloat162(h[0], h[1]);
    *reinterpret_cast<__nv_bfloat162*>(dHo + i + 2) = __halves2bfloat162(h[2], h[3]);
    *reinterpret_cast<__nv_bfloat162*>(dLo + i)     = __halves2bfloat162(l[0], l[1]);
    *reinterpret_cast<__nv_bfloat162*>(dLo + i + 2) = __halves2bfloat162(l[2], l[3]);
}

// transpose a 2048x2048 bf16 matrix pair (z=0: hi, z=1: lo), 64x64 tiles
__global__ void transpose_kernel(const __nv_bfloat16* __restrict__ sH,
                                 const __nv_bfloat16* __restrict__ sL,
                                 __nv_bfloat16* __restrict__ dHo,
                                 __nv_bfloat16* __restrict__ dLo)
{
    __shared__ uint32_t tsm[64][33];
    const __nv_bfloat16* src = blockIdx.z ? sL : sH;
    __nv_bfloat16*       dst = blockIdx.z ? dLo : dHo;
    const int r0 = blockIdx.y * 64, c0 = blockIdx.x * 64;
    const int t = threadIdx.x;
    const int x2 = t & 31, y0 = t >> 5;
    for (int yy = y0; yy < 64; yy += 8)
        tsm[yy][x2] = *reinterpret_cast<const uint32_t*>(
            src + (size_t)(r0 + yy) * GK + c0 + x2 * 2);
    __syncthreads();
    for (int idx = t; idx < 64 * 32; idx += 256) {
        int n = idx >> 5, jp = idx & 31;
        uint32_t a = tsm[2 * jp][n >> 1];
        uint32_t b = tsm[2 * jp + 1][n >> 1];
        uint32_t lo = (n & 1) ? (a >> 16) : (a & 0xffffu);
        uint32_t hi = (n & 1) ? (b >> 16) : (b & 0xffffu);
        *reinterpret_cast<uint32_t*>(dst + (size_t)(c0 + n) * GK + r0 + 2 * jp) =
            lo | (hi << 16);
    }
}

// ============================================================================
// Host orchestration (graph-capturable: kernel launches only)
// ============================================================================
static const float PE_COEF[8][3] = {
    {7.2086f, -15.5131f, 9.0178f}, {3.9623f, -2.5813f, 0.4542f},
    {3.9466f, -2.5765f, 0.4544f}, {3.8991f, -2.5671f, 0.4566f},
    {3.7186f, -2.5308f, 0.4653f}, {3.1390f, -2.3073f, 0.4733f},
    {2.1715f, -1.5246f, 0.3885f}, {1.8648f, -1.2224f, 0.3577f},
};

struct BPtr { __nv_bfloat16 *h, *l; };

static inline void run_gemm(int Mrows, BPtr A, BPtr B,
                            BPtr out, float* oF, BPtr D,
                            float alpha, float beta, int alphaIdx, int sumsq)
{
    cudaFuncSetAttribute(gemm_bf16x3_kernel,
                         cudaFuncAttributeMaxDynamicSharedMemorySize, SMEM_NEED);
    dim3 grid(GK / 128, Mrows / 128), block(256);
    gemm_bf16x3_kernel<<<grid, block, SMEM_NEED>>>(
        A.h, A.l, B.h, B.l, out.h, out.l, oF, D.h, D.l,
        alpha, beta, alphaIdx, sumsq);
}

extern "C" void kernel_launch(void* const* d_in, const int* in_sizes, int n_in,
                              void* d_out, int out_size)
{
    const float* x      = (const float*)d_in[0];
    const float* weight = (const float*)d_in[1];
    const float* gamma  = (const float*)d_in[2];
    float*       out    = (float*)d_out;
    const int M_out = in_sizes[0] / GK;      // 8192

    auto sym = [](const void* s) {
        void* p; cudaGetSymbolAddress(&p, s); return (__nv_bfloat16*)p;
    };
    BPtr w  = {sym(g_wh),  sym(g_wl)};
    BPtr u0 = {sym(g_u0h), sym(g_u0l)};
    BPtr u1 = {sym(g_u1h), sym(g_u1l)};
    BPtr t0 = {sym(g_t0h), sym(g_t0l)};
    BPtr t1 = {sym(g_t1h), sym(g_t1l)};
    BPtr g  = {sym(g_gh),  sym(g_gl)};
    BPtr e  = {sym(g_eh),  sym(g_el)};
    BPtr X  = {sym(g_xh),  sym(g_xl)};
    BPtr nil = {nullptr, nullptr};

    // ---- w_norm = ||(W W^T)^2||_F^0.25 + eps ----
    zero_accum_kernel<<<1, 1>>>();
    split_kernel<<<MAT / 4 / 256, 256>>>(weight, w.h, w.l, -1);
    run_gemm(GK, w, w, g, nullptr, nil, 1.0f, 0.0f, -1, 0);      // gram -> g
    run_gemm(GK, g, g, nil, nullptr, nil, 1.0f, 0.0f, -1, 1);    // sumsq(gram^2)
    finalize_kernel<<<1, 1>>>(gamma);

    // ---- U = weight / w_norm ; X split ; U^T ----
    split_kernel<<<MAT / 4 / 256, 256>>>(weight, u0.h, u0.l, 1);
    split_kernel<<<XMAT / 4 / 256, 256>>>(x, X.h, X.l, -1);
    transpose_kernel<<<dim3(32, 32, 2), 256>>>(u0.h, u0.l, t0.h, t0.l);

    // ---- 8 Polar Express iterations ----
    BPtr U = u0, Un = u1, UT = t0, UTn = t1;
    for (int it = 0; it < 8; it++) {
        float a = PE_COEF[it][0], bb = PE_COEF[it][1], c = PE_COEF[it][2];
        run_gemm(GK, UT, UT, g, nullptr, nil, 1.0f, 0.0f, -1, 0);     // g = U^T U
        run_gemm(GK, g,  g,  e, nullptr, g,   c,    bb,   -1, 0);     // T = c g^2 + b g
        run_gemm(GK, U,  e,  Un, nullptr, U,  1.0f, a,    -1, 0);     // Un = U T + a U
        if (it < 7)
            transpose_kernel<<<dim3(32, 32, 2), 256>>>(Un.h, Un.l, UTn.h, UTn.l);
        BPtr tp;
        tp = U; U = Un; Un = tp;
        tp = UT; UT = UTn; UTn = tp;
    }

    // ---- out = (w_norm * gamma) * X @ U^T ----
    run_gemm(M_out, X, U, nil, out, nil, 1.0f, 0.0f, 2, 0);
}